// round 13
// baseline (speedup 1.0000x reference)
#include <cuda_runtime.h>
#include <cuda_fp16.h>
#include <math.h>
#include <stdint.h>

#define BATCH 4
#define SEQ   2048
#define DMODEL 1024
#define NH    16
#define DK    64
#define MROWS (BATCH*SEQ)   // 8192

// Scratch (halves unless noted)
__device__ __align__(256) __half g_Qh [BATCH*NH*SEQ*DK];   // [bh][s][dk], pre-scaled by 1/8
__device__ __align__(256) __half g_Kh [BATCH*NH*SEQ*DK];   // [bh][s][dk]
__device__ __align__(256) __half g_Vth[BATCH*NH*SEQ*DK];   // [bh][dk][s]  (transposed!)
__device__ __align__(256) __half g_Ch [MROWS*DMODEL];      // ctx [m][n]
__device__ __align__(256) __half g_Xh [MROWS*DMODEL];      // x  [m][k]
__device__ __align__(256) __half g_WqT[DMODEL*DMODEL];     // [n][k]
__device__ __align__(256) __half g_WkT[DMODEL*DMODEL];
__device__ __align__(256) __half g_WvT[DMODEL*DMODEL];
__device__ __align__(256) __half g_WoT[DMODEL*DMODEL];

// ---------------------------------------------------------------------------
__device__ __forceinline__ void mma_f16(float d[4], const unsigned a[4], const unsigned b[2]) {
    asm volatile(
        "mma.sync.aligned.m16n8k16.row.col.f32.f16.f16.f32 "
        "{%0,%1,%2,%3}, {%4,%5,%6,%7}, {%8,%9}, {%0,%1,%2,%3};"
        : "+f"(d[0]), "+f"(d[1]), "+f"(d[2]), "+f"(d[3])
        : "r"(a[0]), "r"(a[1]), "r"(a[2]), "r"(a[3]), "r"(b[0]), "r"(b[1]));
}
__device__ __forceinline__ void ldm_x4(unsigned& r0, unsigned& r1, unsigned& r2, unsigned& r3,
                                       const __half* p) {
    uint32_t addr = (uint32_t)__cvta_generic_to_shared(p);
    asm volatile("ldmatrix.sync.aligned.m8n8.x4.shared.b16 {%0,%1,%2,%3}, [%4];"
                 : "=r"(r0), "=r"(r1), "=r"(r2), "=r"(r3) : "r"(addr));
}

__device__ __forceinline__ void cp16(void* smem, const void* gmem) {
    unsigned s = (unsigned)__cvta_generic_to_shared(smem);
    asm volatile("cp.async.cg.shared.global [%0], [%1], 16;" :: "r"(s), "l"(gmem));
}
#define CP_COMMIT()  asm volatile("cp.async.commit_group;")
#define CP_WAIT1()   asm volatile("cp.async.wait_group 1;")
#define CP_WAIT0()   asm volatile("cp.async.wait_group 0;")

// Pitches in halves. ldmatrix conflict-free: PW=40h (20 words) and PH=72h (36
// words) spread 8 successive 16B row-chunks across all 32 banks; rows are
// 16B-aligned (80B / 144B pitches).
#define PW 40
#define PH 72

// ---------------------------------------------------------------------------
// Prep kernels
// ---------------------------------------------------------------------------
__global__ void cvt_x_h(const float* __restrict__ src, __half* __restrict__ dst, int n4)
{
    int i = blockIdx.x * blockDim.x + threadIdx.x;
    if (i < n4) {
        float4 v = ((const float4*)src)[i];
        ((__half2*)dst)[2*i]   = __floats2half2_rn(v.x, v.y);
        ((__half2*)dst)[2*i+1] = __floats2half2_rn(v.z, v.w);
    }
}

// W[h][k][dk] -> WT[n=h*64+dk][k], tiled smem transpose, all 3 matrices.
__global__ void transpose_wqkv_t(const float* __restrict__ Wq,
                                 const float* __restrict__ Wk,
                                 const float* __restrict__ Wv)
{
    __shared__ __half tile[32][33];
    const int mat = blockIdx.z >> 4;
    const int h   = blockIdx.z & 15;
    const float* src = (mat == 0) ? Wq : (mat == 1) ? Wk : Wv;
    __half* dst      = (mat == 0) ? g_WqT : (mat == 1) ? g_WkT : g_WvT;
    const int k0 = blockIdx.x * 32, d0 = blockIdx.y * 32;
    const int tx = threadIdx.x, ty = threadIdx.y;
    #pragma unroll
    for (int i = 0; i < 4; i++) {
        int kk = ty + i * 8;
        tile[tx][kk] = __float2half_rn(src[h * 65536 + (k0 + kk) * 64 + d0 + tx]);
    }
    __syncthreads();
    #pragma unroll
    for (int i = 0; i < 4; i++) {
        int dd = ty + i * 8;
        dst[(size_t)(h * 64 + d0 + dd) * 1024 + k0 + tx] = tile[dd][tx];
    }
}

// Wo[k][n] -> WT[n][k], tiled.
__global__ void transpose_wo_t(const float* __restrict__ src)
{
    __shared__ __half tile[32][33];
    const int k0 = blockIdx.x * 32, n0 = blockIdx.y * 32;
    const int tx = threadIdx.x, ty = threadIdx.y;
    #pragma unroll
    for (int i = 0; i < 4; i++) {
        int kk = ty + i * 8;
        tile[tx][kk] = __float2half_rn(src[(size_t)(k0 + kk) * 1024 + n0 + tx]);
    }
    __syncthreads();
    #pragma unroll
    for (int i = 0; i < 4; i++) {
        int dd = ty + i * 8;
        g_WoT[(size_t)(n0 + dd) * 1024 + k0 + tx] = tile[dd][tx];
    }
}

// ---------------------------------------------------------------------------
// Fused QKV GEMM: tile 128x128, warp 32x64, fp16 mma + ldmatrix.
// 3-slot cp.async ring, issue depth 1, ONE barrier per chunk.
// grid (64, 24), block 256. dyn smem 61440 B.
// ---------------------------------------------------------------------------
#define STGH (128*PW + 128*PW)          // halves per stage (A+B) = 10240
#define GEMM_SMEM (3 * STGH * 2)        // 61440 B

__global__ void __launch_bounds__(256, 2) qkv_proj(
    const float* __restrict__ bq, const float* __restrict__ bk,
    const float* __restrict__ bv)
{
    extern __shared__ __align__(16) __half smh[];

    const int row0 = blockIdx.x * 128;
    const int n0g  = blockIdx.y * 128;
    const int mat  = n0g >> 10;
    const int nm   = n0g & 1023;
    const __half* WT; const float* bias;
    if (mat == 0)      { WT = g_WqT; bias = bq; }
    else if (mat == 1) { WT = g_WkT; bias = bk; }
    else               { WT = g_WvT; bias = bv; }

    const int tid = threadIdx.x;
    const int w  = tid >> 5;
    const int l  = tid & 31;
    const int lr = l & 3;
    const int wm = w >> 1, wn = w & 1;

    const int a_row = l & 15;
    const int a_ko  = (l >> 4) << 3;
    const int b_nr  = (l & 7) + ((l >> 4) << 3);
    const int b_ko  = ((l >> 3) & 1) << 3;

    float acc[2][8][4] = {};

    auto stage = [&](int c, int s) {
        __half* As = smh + s * STGH;
        __half* Bs = As + 128 * PW;
        int k0 = c * 32;
        #pragma unroll
        for (int i = 0; i < 2; i++) {
            int idx = tid + i * 256;
            int r = idx >> 2, j = idx & 3;
            cp16(&As[r * PW + j * 8], g_Xh + (size_t)(row0 + r) * DMODEL + k0 + j * 8);
        }
        #pragma unroll
        for (int i = 0; i < 2; i++) {
            int idx = tid + i * 256;
            int rn = idx >> 2, j = idx & 3;
            cp16(&Bs[rn * PW + j * 8], WT + (size_t)(nm + rn) * DMODEL + k0 + j * 8);
        }
        CP_COMMIT();
    };

    stage(0, 0);

    for (int c = 0; c < 32; c++) {
        if (c + 1 < 32) { stage(c + 1, (c + 1) % 3); CP_WAIT1(); }
        else            { CP_WAIT0(); }
        __syncthreads();   // single barrier: 3-slot ring makes the trailing one unnecessary

        const __half* As = smh + (c % 3) * STGH;
        const __half* Bs = As + 128 * PW;

        #pragma unroll
        for (int kk = 0; kk < 2; kk++) {
            unsigned a[2][4], b[8][2];
            #pragma unroll
            for (int mi = 0; mi < 2; mi++)
                ldm_x4(a[mi][0], a[mi][1], a[mi][2], a[mi][3],
                       &As[(wm * 32 + mi * 16 + a_row) * PW + kk * 16 + a_ko]);
            #pragma unroll
            for (int nj = 0; nj < 4; nj++)
                ldm_x4(b[2*nj][0], b[2*nj][1], b[2*nj+1][0], b[2*nj+1][1],
                       &Bs[(wn * 64 + nj * 16 + b_nr) * PW + kk * 16 + b_ko]);
            #pragma unroll
            for (int mi = 0; mi < 2; mi++)
                #pragma unroll
                for (int ni = 0; ni < 8; ni++)
                    mma_f16(acc[mi][ni], a[mi], b[ni]);
        }
    }

    // epilogue: +bias; Q pre-scaled; V transposed
    const int lq = l >> 2;
    #pragma unroll
    for (int mi = 0; mi < 2; mi++)
        #pragma unroll
        for (int rh = 0; rh < 2; rh++) {
            int m = row0 + wm * 32 + mi * 16 + lq + rh * 8;
            int bi = m >> 11, s = m & (SEQ - 1);
            #pragma unroll
            for (int ni = 0; ni < 8; ni++) {
                int col = nm + wn * 64 + ni * 8 + 2 * lr;
                int h = col >> 6, dk = col & 63;
                float2 bv2 = *(const float2*)(bias + col);
                float v0 = acc[mi][ni][rh * 2 + 0] + bv2.x;
                float v1 = acc[mi][ni][rh * 2 + 1] + bv2.y;
                size_t bh = (size_t)(bi * NH + h);
                if (mat == 0) {
                    *(__half2*)(g_Qh + (bh * SEQ + s) * DK + dk) =
                        __floats2half2_rn(v0 * 0.125f, v1 * 0.125f);
                } else if (mat == 1) {
                    *(__half2*)(g_Kh + (bh * SEQ + s) * DK + dk) =
                        __floats2half2_rn(v0, v1);
                } else {
                    g_Vth[(bh * DK + dk)     * SEQ + s] = __float2half_rn(v0);
                    g_Vth[(bh * DK + dk + 1) * SEQ + s] = __float2half_rn(v1);
                }
            }
        }
}

// ---------------------------------------------------------------------------
// Causal flash attention fp16 + ldmatrix. q-tile 128, kv-tile 64.
// 3-slot KV ring, ONE barrier per step. grid (16, 64), block 256.
// dyn smem 92160 B (2 CTAs/SM).
// ---------------------------------------------------------------------------
#define KVSTGH (64*PH + 64*PH)                       // 9216 halves per KV slot
#define ATTN_SMEM ((256*PH + 3*KVSTGH) * 2)          // 92160 B

__global__ void __launch_bounds__(256, 2) attn_flash()
{
    extern __shared__ __align__(16) __half smh[];
    __half* Qs  = smh;                     // [q][dk] 128 x 72
    __half* Ps  = smh + 128 * PH;          // [q][s]  128 x 72
    __half* KVB = smh + 256 * PH;          // 3 KV slots

    const int qt  = blockIdx.x;
    const int bh  = blockIdx.y;
    const int tid = threadIdx.x;
    const int w   = tid >> 5;
    const int l   = tid & 31;
    const int lq = l >> 2, lr = l & 3;

    const int a_row = l & 15;
    const int a_ko  = (l >> 4) << 3;
    const int b_nr  = (l & 7) + ((l >> 4) << 3);
    const int b_ko  = ((l >> 3) & 1) << 3;

    const __half* Qg  = g_Qh  + (size_t)bh * SEQ * DK + (size_t)qt * 128 * DK;
    const __half* Kg  = g_Kh  + (size_t)bh * SEQ * DK;
    const __half* Vtg = g_Vth + (size_t)bh * DK * SEQ;

    const int jmax = 2 * qt + 1;

    // stage_kv WITHOUT commit (caller commits, so Q can share group 0)
    auto stage_kv = [&](int j, int slot) {
        __half* Ks = KVB + slot * KVSTGH;
        __half* Vt = Ks + 64 * PH;
        #pragma unroll
        for (int i = 0; i < 2; i++) {
            int idx = tid + i * 256;
            int r = idx >> 3, j2 = idx & 7;
            cp16(&Ks[r * PH + j2 * 8], Kg + (size_t)(j * 64 + r) * DK + j2 * 8);
        }
        #pragma unroll
        for (int i = 0; i < 2; i++) {
            int idx = tid + i * 256;
            int r = idx >> 3, j2 = idx & 7;
            cp16(&Vt[r * PH + j2 * 8], Vtg + (size_t)r * SEQ + j * 64 + j2 * 8);
        }
    };

    // Group 0 = Q tile + KV slot 0 (single commit: wait_group counting stays exact)
    #pragma unroll
    for (int i = 0; i < 4; i++) {
        int idx = tid + i * 256;
        int r = idx >> 3, j2 = idx & 7;
        cp16(&Qs[r * PH + j2 * 8], Qg + (size_t)r * DK + j2 * 8);
    }
    stage_kv(0, 0);
    CP_COMMIT();

    float m0 = -INFINITY, m1 = -INFINITY;
    float l0 = 0.f, l1 = 0.f;
    float o[8][4] = {};

    for (int j = 0; j <= jmax; j++) {
        if (j + 1 <= jmax) { stage_kv(j + 1, (j + 1) % 3); CP_COMMIT(); CP_WAIT1(); }
        else               { CP_WAIT0(); }
        __syncthreads();   // single barrier per step (3-slot ring)

        const __half* Ks = KVB + (j % 3) * KVSTGH;
        const __half* Vt = Ks + 64 * PH;

        // S = Q K^T
        float s[8][4] = {};
        #pragma unroll
        for (int kk = 0; kk < 4; kk++) {
            unsigned a[4], b[8][2];
            ldm_x4(a[0], a[1], a[2], a[3],
                   &Qs[(w * 16 + a_row) * PH + kk * 16 + a_ko]);
            #pragma unroll
            for (int nj = 0; nj < 4; nj++)
                ldm_x4(b[2*nj][0], b[2*nj][1], b[2*nj+1][0], b[2*nj+1][1],
                       &Ks[(nj * 16 + b_nr) * PH + kk * 16 + b_ko]);
            #pragma unroll
            for (int ni = 0; ni < 8; ni++)
                mma_f16(s[ni], a, b[ni]);
        }

        // causal mask (global col = 64j + c, row = 128qt + r)
        if (j >= 2 * qt) {
            int joff = (j - 2 * qt) << 6;
            int r1m = w * 16 + lq, r2m = r1m + 8;
            #pragma unroll
            for (int ni = 0; ni < 8; ni++) {
                int c0 = ni * 8 + 2 * lr + joff;
                if (c0     > r1m) s[ni][0] = -INFINITY;
                if (c0 + 1 > r1m) s[ni][1] = -INFINITY;
                if (c0     > r2m) s[ni][2] = -INFINITY;
                if (c0 + 1 > r2m) s[ni][3] = -INFINITY;
            }
        }

        // online softmax (fp32)
        float rm0 = -INFINITY, rm1 = -INFINITY;
        #pragma unroll
        for (int ni = 0; ni < 8; ni++) {
            rm0 = fmaxf(rm0, fmaxf(s[ni][0], s[ni][1]));
            rm1 = fmaxf(rm1, fmaxf(s[ni][2], s[ni][3]));
        }
        rm0 = fmaxf(rm0, __shfl_xor_sync(0xffffffffu, rm0, 1));
        rm0 = fmaxf(rm0, __shfl_xor_sync(0xffffffffu, rm0, 2));
        rm1 = fmaxf(rm1, __shfl_xor_sync(0xffffffffu, rm1, 1));
        rm1 = fmaxf(rm1, __shfl_xor_sync(0xffffffffu, rm1, 2));

        float mn0 = fmaxf(m0, rm0), mn1 = fmaxf(m1, rm1);
        float corr0 = __expf(m0 - mn0), corr1 = __expf(m1 - mn1);
        m0 = mn0; m1 = mn1;

        float rs0 = 0.f, rs1 = 0.f;
        const int r1 = w * 16 + lq, r2 = r1 + 8;
        #pragma unroll
        for (int ni = 0; ni < 8; ni++) {
            float p0 = __expf(s[ni][0] - mn0);
            float p1 = __expf(s[ni][1] - mn0);
            float p2 = __expf(s[ni][2] - mn1);
            float p3 = __expf(s[ni][3] - mn1);
            rs0 += p0 + p1; rs1 += p2 + p3;
            int c = ni * 8 + 2 * lr;
            *(__half2*)&Ps[r1 * PH + c] = __floats2half2_rn(p0, p1);
            *(__half2*)&Ps[r2 * PH + c] = __floats2half2_rn(p2, p3);
            o[ni][0] *= corr0; o[ni][1] *= corr0;
            o[ni][2] *= corr1; o[ni][3] *= corr1;
        }
        rs0 += __shfl_xor_sync(0xffffffffu, rs0, 1);
        rs0 += __shfl_xor_sync(0xffffffffu, rs0, 2);
        rs1 += __shfl_xor_sync(0xffffffffu, rs1, 1);
        rs1 += __shfl_xor_sync(0xffffffffu, rs1, 2);
        l0 = l0 * corr0 + rs0;
        l1 = l1 * corr1 + rs1;

        __syncwarp();   // Ps rows warp-private: order stores before ldmatrix

        // O += P V
        #pragma unroll
        for (int kk = 0; kk < 4; kk++) {
            unsigned a[4], b[8][2];
            ldm_x4(a[0], a[1], a[2], a[3],
                   &Ps[(w * 16 + a_row) * PH + kk * 16 + a_ko]);
            #pragma unroll
            for (int nj = 0; nj < 4; nj++)
                ldm_x4(b[2*nj][0], b[2*nj][1], b[2*nj+1][0], b[2*nj+1][1],
                       &Vt[(nj * 16 + b_nr) * PH + kk * 16 + b_ko]);
            #pragma unroll
            for (int ni = 0; ni < 8; ni++)
                mma_f16(o[ni], a, b[ni]);
        }
    }

    // normalize + write ctx [B, S, H*DK] as half
    const int b_idx = bh / NH, h = bh % NH;
    const float inv0 = 1.0f / l0, inv1 = 1.0f / l1;
    const int r1 = w * 16 + lq, r2 = r1 + 8;
    __half* c1 = g_Ch + (size_t)(b_idx * SEQ + qt * 128 + r1) * DMODEL + h * DK;
    __half* c2 = g_Ch + (size_t)(b_idx * SEQ + qt * 128 + r2) * DMODEL + h * DK;
    #pragma unroll
    for (int ni = 0; ni < 8; ni++) {
        int c = ni * 8 + 2 * lr;
        *(__half2*)(c1 + c) = __floats2half2_rn(o[ni][0] * inv0, o[ni][1] * inv0);
        *(__half2*)(c2 + c) = __floats2half2_rn(o[ni][2] * inv1, o[ni][3] * inv1);
    }
}

// ---------------------------------------------------------------------------
// Output projection: tile 128x128, fp16 + ldmatrix, 3-slot ring, 1 barrier.
// grid (64, 8), block 256. dyn smem 61440 B.
// ---------------------------------------------------------------------------
__global__ void __launch_bounds__(256, 2) out_proj(
    const float* __restrict__ bo, float* __restrict__ out)
{
    extern __shared__ __align__(16) __half smh[];

    const int row0 = blockIdx.x * 128, n0 = blockIdx.y * 128;
    const int tid = threadIdx.x;
    const int w  = tid >> 5;
    const int l  = tid & 31;
    const int lr = l & 3;
    const int wm = w >> 1, wn = w & 1;

    const int a_row = l & 15;
    const int a_ko  = (l >> 4) << 3;
    const int b_nr  = (l & 7) + ((l >> 4) << 3);
    const int b_ko  = ((l >> 3) & 1) << 3;

    float acc[2][8][4] = {};

    auto stage = [&](int c, int s) {
        __half* As = smh + s * STGH;
        __half* Bs = As + 128 * PW;
        int k0 = c * 32;
        #pragma unroll
        for (int i = 0; i < 2; i++) {
            int idx = tid + i * 256;
            int r = idx >> 2, j = idx & 3;
            cp16(&As[r * PW + j * 8], g_Ch + (size_t)(row0 + r) * DMODEL + k0 + j * 8);
        }
        #pragma unroll
        for (int i = 0; i < 2; i++) {
            int idx = tid + i * 256;
            int rn = idx >> 2, j = idx & 3;
            cp16(&Bs[rn * PW + j * 8], g_WoT + (size_t)(n0 + rn) * DMODEL + k0 + j * 8);
        }
        CP_COMMIT();
    };

    stage(0, 0);

    for (int c = 0; c < 32; c++) {
        if (c + 1 < 32) { stage(c + 1, (c + 1) % 3); CP_WAIT1(); }
        else            { CP_WAIT0(); }
        __syncthreads();

        const __half* As = smh + (c % 3) * STGH;
        const __half* Bs = As + 128 * PW;

        #pragma unroll
        for (int kk = 0; kk < 2; kk++) {
            unsigned a[2][4], b[8][2];
            #pragma unroll
            for (int mi = 0; mi < 2; mi++)
                ldm_x4(a[mi][0], a[mi][1], a[mi][2], a[mi][3],
                       &As[(wm * 32 + mi * 16 + a_row) * PW + kk * 16 + a_ko]);
            #pragma unroll
            for (int nj = 0; nj < 4; nj++)
                ldm_x4(b[2*nj][0], b[2*nj][1], b[2*nj+1][0], b[2*nj+1][1],
                       &Bs[(wn * 64 + nj * 16 + b_nr) * PW + kk * 16 + b_ko]);
            #pragma unroll
            for (int mi = 0; mi < 2; mi++)
                #pragma unroll
                for (int ni = 0; ni < 8; ni++)
                    mma_f16(acc[mi][ni], a[mi], b[ni]);
        }
    }

    const int lq = l >> 2;
    #pragma unroll
    for (int mi = 0; mi < 2; mi++)
        #pragma unroll
        for (int rh = 0; rh < 2; rh++) {
            int m = row0 + wm * 32 + mi * 16 + lq + rh * 8;
            #pragma unroll
            for (int ni = 0; ni < 8; ni++) {
                int col = n0 + wn * 64 + ni * 8 + 2 * lr;
                float2 bv2 = *(const float2*)(bo + col);
                float2 v = make_float2(acc[mi][ni][rh * 2 + 0] + bv2.x,
                                       acc[mi][ni][rh * 2 + 1] + bv2.y);
                *(float2*)(out + (size_t)m * DMODEL + col) = v;
            }
        }
}

// ---------------------------------------------------------------------------
extern "C" void kernel_launch(void* const* d_in, const int* in_sizes, int n_in,
                              void* d_out, int out_size)
{
    const float* x  = (const float*)d_in[0];
    const float* Wq = (const float*)d_in[1];
    const float* bq = (const float*)d_in[2];
    const float* Wk = (const float*)d_in[3];
    const float* bk = (const float*)d_in[4];
    const float* Wv = (const float*)d_in[5];
    const float* bv = (const float*)d_in[6];
    const float* Wo = (const float*)d_in[7];
    const float* bo = (const float*)d_in[8];
    float* out = (float*)d_out;

    cudaFuncSetAttribute(qkv_proj,   cudaFuncAttributeMaxDynamicSharedMemorySize, GEMM_SMEM);
    cudaFuncSetAttribute(attn_flash, cudaFuncAttributeMaxDynamicSharedMemorySize, ATTN_SMEM);
    cudaFuncSetAttribute(out_proj,   cudaFuncAttributeMaxDynamicSharedMemorySize, GEMM_SMEM);

    __half* gx;
    cudaGetSymbolAddress((void**)&gx, g_Xh);

    const int NX4 = MROWS * DMODEL / 4;
    cvt_x_h<<<(NX4 + 255) / 256, 256>>>(x, gx, NX4);
    transpose_wqkv_t<<<dim3(32, 2, 48), dim3(32, 8)>>>(Wq, Wk, Wv);
    transpose_wo_t  <<<dim3(32, 32),    dim3(32, 8)>>>(Wo);

    qkv_proj<<<dim3(MROWS / 128, 24), 256, GEMM_SMEM>>>(bq, bk, bv);
    attn_flash<<<dim3(SEQ / 128, BATCH * NH), 256, ATTN_SMEM>>>();
    out_proj<<<dim3(MROWS / 128, 8), 256, GEMM_SMEM>>>(bo, out);
}

// round 15
// speedup vs baseline: 1.4340x; 1.4340x over previous
#include <cuda_runtime.h>
#include <cuda_fp16.h>
#include <math.h>
#include <stdint.h>

#define BATCH 4
#define SEQ   2048
#define DMODEL 1024
#define NH    16
#define DK    64
#define MROWS (BATCH*SEQ)   // 8192

// Scratch (halves unless noted)
__device__ __align__(256) __half g_Qh [BATCH*NH*SEQ*DK];   // [bh][s][dk], pre-scaled by 1/8
__device__ __align__(256) __half g_Kh [BATCH*NH*SEQ*DK];   // [bh][s][dk]
__device__ __align__(256) __half g_Vth[BATCH*NH*SEQ*DK];   // [bh][dk][s]  (transposed!)
__device__ __align__(256) __half g_Ch [MROWS*DMODEL];      // ctx [m][n]
__device__ __align__(256) __half g_Xh [MROWS*DMODEL];      // x  [m][k]
__device__ __align__(256) __half g_WqT[DMODEL*DMODEL];     // [n][k]
__device__ __align__(256) __half g_WkT[DMODEL*DMODEL];
__device__ __align__(256) __half g_WvT[DMODEL*DMODEL];
__device__ __align__(256) __half g_WoT[DMODEL*DMODEL];

// ---------------------------------------------------------------------------
__device__ __forceinline__ void mma_f16(float d[4], const unsigned a[4], const unsigned b[2]) {
    asm volatile(
        "mma.sync.aligned.m16n8k16.row.col.f32.f16.f16.f32 "
        "{%0,%1,%2,%3}, {%4,%5,%6,%7}, {%8,%9}, {%0,%1,%2,%3};"
        : "+f"(d[0]), "+f"(d[1]), "+f"(d[2]), "+f"(d[3])
        : "r"(a[0]), "r"(a[1]), "r"(a[2]), "r"(a[3]), "r"(b[0]), "r"(b[1]));
}
__device__ __forceinline__ void ldm_x4(unsigned& r0, unsigned& r1, unsigned& r2, unsigned& r3,
                                       const __half* p) {
    uint32_t addr = (uint32_t)__cvta_generic_to_shared(p);
    asm volatile("ldmatrix.sync.aligned.m8n8.x4.shared.b16 {%0,%1,%2,%3}, [%4];"
                 : "=r"(r0), "=r"(r1), "=r"(r2), "=r"(r3) : "r"(addr));
}

__device__ __forceinline__ void cp16(void* smem, const void* gmem) {
    unsigned s = (unsigned)__cvta_generic_to_shared(smem);
    asm volatile("cp.async.cg.shared.global [%0], [%1], 16;" :: "r"(s), "l"(gmem));
}
#define CP_COMMIT()  asm volatile("cp.async.commit_group;")
#define CP_WAIT2()   asm volatile("cp.async.wait_group 2;")
#define CP_WAIT1()   asm volatile("cp.async.wait_group 1;")
#define CP_WAIT0()   asm volatile("cp.async.wait_group 0;")

// Pitches in halves. ldmatrix conflict-free: PW=40h (20 words) and PH=72h (36
// words) spread 8 successive 16B row-chunks across all 32 banks; rows are
// 16B-aligned (80B / 144B pitches).
#define PW 40
#define PH 72

// ---------------------------------------------------------------------------
// Prep kernels
// ---------------------------------------------------------------------------
__global__ void cvt_x_h(const float* __restrict__ src, __half* __restrict__ dst, int n4)
{
    int i = blockIdx.x * blockDim.x + threadIdx.x;
    if (i < n4) {
        float4 v = ((const float4*)src)[i];
        ((__half2*)dst)[2*i]   = __floats2half2_rn(v.x, v.y);
        ((__half2*)dst)[2*i+1] = __floats2half2_rn(v.z, v.w);
    }
}

// W[h][k][dk] -> WT[n=h*64+dk][k], tiled smem transpose, all 3 matrices.
__global__ void transpose_wqkv_t(const float* __restrict__ Wq,
                                 const float* __restrict__ Wk,
                                 const float* __restrict__ Wv)
{
    __shared__ __half tile[32][33];
    const int mat = blockIdx.z >> 4;
    const int h   = blockIdx.z & 15;
    const float* src = (mat == 0) ? Wq : (mat == 1) ? Wk : Wv;
    __half* dst      = (mat == 0) ? g_WqT : (mat == 1) ? g_WkT : g_WvT;
    const int k0 = blockIdx.x * 32, d0 = blockIdx.y * 32;
    const int tx = threadIdx.x, ty = threadIdx.y;
    #pragma unroll
    for (int i = 0; i < 4; i++) {
        int kk = ty + i * 8;
        tile[tx][kk] = __float2half_rn(src[h * 65536 + (k0 + kk) * 64 + d0 + tx]);
    }
    __syncthreads();
    #pragma unroll
    for (int i = 0; i < 4; i++) {
        int dd = ty + i * 8;
        dst[(size_t)(h * 64 + d0 + dd) * 1024 + k0 + tx] = tile[dd][tx];
    }
}

// Wo[k][n] -> WT[n][k], tiled.
__global__ void transpose_wo_t(const float* __restrict__ src)
{
    __shared__ __half tile[32][33];
    const int k0 = blockIdx.x * 32, n0 = blockIdx.y * 32;
    const int tx = threadIdx.x, ty = threadIdx.y;
    #pragma unroll
    for (int i = 0; i < 4; i++) {
        int kk = ty + i * 8;
        tile[tx][kk] = __float2half_rn(src[(size_t)(k0 + kk) * 1024 + n0 + tx]);
    }
    __syncthreads();
    #pragma unroll
    for (int i = 0; i < 4; i++) {
        int dd = ty + i * 8;
        g_WoT[(size_t)(n0 + dd) * 1024 + k0 + tx] = tile[dd][tx];
    }
}

// ---------------------------------------------------------------------------
// Fused QKV GEMM: tile 128x128, warp 32x64, fp16 mma + ldmatrix.
// 3-slot ring, issue depth 2, BOTH barriers kept (R12 structure).
// grid (64, 24), block 256. dyn smem 61440 B.
// ---------------------------------------------------------------------------
#define STGH (128*PW + 128*PW)          // halves per stage (A+B) = 10240
#define GEMM_SMEM (3 * STGH * 2)        // 61440 B

__global__ void __launch_bounds__(256, 2) qkv_proj(
    const float* __restrict__ bq, const float* __restrict__ bk,
    const float* __restrict__ bv)
{
    extern __shared__ __align__(16) __half smh[];

    const int row0 = blockIdx.x * 128;
    const int n0g  = blockIdx.y * 128;
    const int mat  = n0g >> 10;
    const int nm   = n0g & 1023;
    const __half* WT; const float* bias;
    if (mat == 0)      { WT = g_WqT; bias = bq; }
    else if (mat == 1) { WT = g_WkT; bias = bk; }
    else               { WT = g_WvT; bias = bv; }

    const int tid = threadIdx.x;
    const int w  = tid >> 5;
    const int l  = tid & 31;
    const int lr = l & 3;
    const int wm = w >> 1, wn = w & 1;

    const int a_row = l & 15;
    const int a_ko  = (l >> 4) << 3;
    const int b_nr  = (l & 7) + ((l >> 4) << 3);
    const int b_ko  = ((l >> 3) & 1) << 3;

    float acc[2][8][4] = {};

    auto stage = [&](int c, int s) {
        __half* As = smh + s * STGH;
        __half* Bs = As + 128 * PW;
        int k0 = c * 32;
        #pragma unroll
        for (int i = 0; i < 2; i++) {
            int idx = tid + i * 256;
            int r = idx >> 2, j = idx & 3;
            cp16(&As[r * PW + j * 8], g_Xh + (size_t)(row0 + r) * DMODEL + k0 + j * 8);
        }
        #pragma unroll
        for (int i = 0; i < 2; i++) {
            int idx = tid + i * 256;
            int rn = idx >> 2, j = idx & 3;
            cp16(&Bs[rn * PW + j * 8], WT + (size_t)(nm + rn) * DMODEL + k0 + j * 8);
        }
        CP_COMMIT();
    };

    stage(0, 0);
    stage(1, 1);

    for (int c = 0; c < 32; c++) {
        if (c + 2 < 32)      { stage(c + 2, (c + 2) % 3); CP_WAIT2(); }
        else if (c + 1 < 32) { CP_WAIT1(); }
        else                 { CP_WAIT0(); }
        __syncthreads();

        const __half* As = smh + (c % 3) * STGH;
        const __half* Bs = As + 128 * PW;

        #pragma unroll
        for (int kk = 0; kk < 2; kk++) {
            unsigned a[2][4], b[8][2];
            #pragma unroll
            for (int mi = 0; mi < 2; mi++)
                ldm_x4(a[mi][0], a[mi][1], a[mi][2], a[mi][3],
                       &As[(wm * 32 + mi * 16 + a_row) * PW + kk * 16 + a_ko]);
            #pragma unroll
            for (int nj = 0; nj < 4; nj++)
                ldm_x4(b[2*nj][0], b[2*nj][1], b[2*nj+1][0], b[2*nj+1][1],
                       &Bs[(wn * 64 + nj * 16 + b_nr) * PW + kk * 16 + b_ko]);
            #pragma unroll
            for (int mi = 0; mi < 2; mi++)
                #pragma unroll
                for (int ni = 0; ni < 8; ni++)
                    mma_f16(acc[mi][ni], a[mi], b[ni]);
        }
        __syncthreads();   // trailing barrier kept: separates LSU phases (R13 lesson)
    }

    // epilogue: +bias; Q pre-scaled; V transposed
    const int lq = l >> 2;
    #pragma unroll
    for (int mi = 0; mi < 2; mi++)
        #pragma unroll
        for (int rh = 0; rh < 2; rh++) {
            int m = row0 + wm * 32 + mi * 16 + lq + rh * 8;
            int bi = m >> 11, s = m & (SEQ - 1);
            #pragma unroll
            for (int ni = 0; ni < 8; ni++) {
                int col = nm + wn * 64 + ni * 8 + 2 * lr;
                int h = col >> 6, dk = col & 63;
                float2 bv2 = *(const float2*)(bias + col);
                float v0 = acc[mi][ni][rh * 2 + 0] + bv2.x;
                float v1 = acc[mi][ni][rh * 2 + 1] + bv2.y;
                size_t bh = (size_t)(bi * NH + h);
                if (mat == 0) {
                    *(__half2*)(g_Qh + (bh * SEQ + s) * DK + dk) =
                        __floats2half2_rn(v0 * 0.125f, v1 * 0.125f);
                } else if (mat == 1) {
                    *(__half2*)(g_Kh + (bh * SEQ + s) * DK + dk) =
                        __floats2half2_rn(v0, v1);
                } else {
                    g_Vth[(bh * DK + dk)     * SEQ + s] = __float2half_rn(v0);
                    g_Vth[(bh * DK + dk + 1) * SEQ + s] = __float2half_rn(v1);
                }
            }
        }
}

// ---------------------------------------------------------------------------
// Causal flash attention fp16 + ldmatrix. q-tile 128, kv-tile 64.
// 3-slot KV ring, depth 2, BOTH barriers kept. grid (16, 64), block 256.
// dyn smem 92160 B (2 CTAs/SM).
// ---------------------------------------------------------------------------
#define KVSTGH (64*PH + 64*PH)                       // 9216 halves per KV slot
#define ATTN_SMEM ((256*PH + 3*KVSTGH) * 2)          // 92160 B

__global__ void __launch_bounds__(256, 2) attn_flash()
{
    extern __shared__ __align__(16) __half smh[];
    __half* Qs  = smh;                     // [q][dk] 128 x 72
    __half* Ps  = smh + 128 * PH;          // [q][s]  128 x 72
    __half* KVB = smh + 256 * PH;          // 3 KV slots

    const int qt  = blockIdx.x;
    const int bh  = blockIdx.y;
    const int tid = threadIdx.x;
    const int w   = tid >> 5;
    const int l   = tid & 31;
    const int lq = l >> 2, lr = l & 3;

    const int a_row = l & 15;
    const int a_ko  = (l >> 4) << 3;
    const int b_nr  = (l & 7) + ((l >> 4) << 3);
    const int b_ko  = ((l >> 3) & 1) << 3;

    const __half* Qg  = g_Qh  + (size_t)bh * SEQ * DK + (size_t)qt * 128 * DK;
    const __half* Kg  = g_Kh  + (size_t)bh * SEQ * DK;
    const __half* Vtg = g_Vth + (size_t)bh * DK * SEQ;

    const int jmax = 2 * qt + 1;

    auto stage_kv = [&](int j, int slot) {
        __half* Ks = KVB + slot * KVSTGH;
        __half* Vt = Ks + 64 * PH;
        #pragma unroll
        for (int i = 0; i < 2; i++) {
            int idx = tid + i * 256;
            int r = idx >> 3, j2 = idx & 7;
            cp16(&Ks[r * PH + j2 * 8], Kg + (size_t)(j * 64 + r) * DK + j2 * 8);
        }
        #pragma unroll
        for (int i = 0; i < 2; i++) {
            int idx = tid + i * 256;
            int r = idx >> 3, j2 = idx & 7;
            cp16(&Vt[r * PH + j2 * 8], Vtg + (size_t)r * SEQ + j * 64 + j2 * 8);
        }
        CP_COMMIT();
    };

    // Group 0 = Q tile + KV slot 0 (single commit); group 1 = KV slot 1.
    #pragma unroll
    for (int i = 0; i < 4; i++) {
        int idx = tid + i * 256;
        int r = idx >> 3, j2 = idx & 7;
        cp16(&Qs[r * PH + j2 * 8], Qg + (size_t)r * DK + j2 * 8);
    }
    stage_kv(0, 0);                         // commits Q+KV0 together
    if (1 <= jmax) stage_kv(1, 1);

    float m0 = -INFINITY, m1 = -INFINITY;
    float l0 = 0.f, l1 = 0.f;
    float o[8][4] = {};

    for (int j = 0; j <= jmax; j++) {
        if (j + 2 <= jmax)      { stage_kv(j + 2, (j + 2) % 3); CP_WAIT2(); }
        else if (j + 1 <= jmax) { CP_WAIT1(); }
        else                    { CP_WAIT0(); }
        __syncthreads();

        const __half* Ks = KVB + (j % 3) * KVSTGH;
        const __half* Vt = Ks + 64 * PH;

        // S = Q K^T
        float s[8][4] = {};
        #pragma unroll
        for (int kk = 0; kk < 4; kk++) {
            unsigned a[4], b[8][2];
            ldm_x4(a[0], a[1], a[2], a[3],
                   &Qs[(w * 16 + a_row) * PH + kk * 16 + a_ko]);
            #pragma unroll
            for (int nj = 0; nj < 4; nj++)
                ldm_x4(b[2*nj][0], b[2*nj][1], b[2*nj+1][0], b[2*nj+1][1],
                       &Ks[(nj * 16 + b_nr) * PH + kk * 16 + b_ko]);
            #pragma unroll
            for (int ni = 0; ni < 8; ni++)
                mma_f16(s[ni], a, b[ni]);
        }

        // causal mask (global col = 64j + c, row = 128qt + r)
        if (j >= 2 * qt) {
            int joff = (j - 2 * qt) << 6;
            int r1m = w * 16 + lq, r2m = r1m + 8;
            #pragma unroll
            for (int ni = 0; ni < 8; ni++) {
                int c0 = ni * 8 + 2 * lr + joff;
                if (c0     > r1m) s[ni][0] = -INFINITY;
                if (c0 + 1 > r1m) s[ni][1] = -INFINITY;
                if (c0     > r2m) s[ni][2] = -INFINITY;
                if (c0 + 1 > r2m) s[ni][3] = -INFINITY;
            }
        }

        // online softmax (fp32)
        float rm0 = -INFINITY, rm1 = -INFINITY;
        #pragma unroll
        for (int ni = 0; ni < 8; ni++) {
            rm0 = fmaxf(rm0, fmaxf(s[ni][0], s[ni][1]));
            rm1 = fmaxf(rm1, fmaxf(s[ni][2], s[ni][3]));
        }
        rm0 = fmaxf(rm0, __shfl_xor_sync(0xffffffffu, rm0, 1));
        rm0 = fmaxf(rm0, __shfl_xor_sync(0xffffffffu, rm0, 2));
        rm1 = fmaxf(rm1, __shfl_xor_sync(0xffffffffu, rm1, 1));
        rm1 = fmaxf(rm1, __shfl_xor_sync(0xffffffffu, rm1, 2));

        float mn0 = fmaxf(m0, rm0), mn1 = fmaxf(m1, rm1);
        float corr0 = __expf(m0 - mn0), corr1 = __expf(m1 - mn1);
        m0 = mn0; m1 = mn1;

        float rs0 = 0.f, rs1 = 0.f;
        const int r1 = w * 16 + lq, r2 = r1 + 8;
        #pragma unroll
        for (int ni = 0; ni < 8; ni++) {
            float p0 = __expf(s[ni][0] - mn0);
            float p1 = __expf(s[ni][1] - mn0);
            float p2 = __expf(s[ni][2] - mn1);
            float p3 = __expf(s[ni][3] - mn1);
            rs0 += p0 + p1; rs1 += p2 + p3;
            int c = ni * 8 + 2 * lr;
            *(__half2*)&Ps[r1 * PH + c] = __floats2half2_rn(p0, p1);
            *(__half2*)&Ps[r2 * PH + c] = __floats2half2_rn(p2, p3);
            o[ni][0] *= corr0; o[ni][1] *= corr0;
            o[ni][2] *= corr1; o[ni][3] *= corr1;
        }
        rs0 += __shfl_xor_sync(0xffffffffu, rs0, 1);
        rs0 += __shfl_xor_sync(0xffffffffu, rs0, 2);
        rs1 += __shfl_xor_sync(0xffffffffu, rs1, 1);
        rs1 += __shfl_xor_sync(0xffffffffu, rs1, 2);
        l0 = l0 * corr0 + rs0;
        l1 = l1 * corr1 + rs1;

        __syncwarp();   // Ps rows warp-private: order stores before ldmatrix

        // O += P V
        #pragma unroll
        for (int kk = 0; kk < 4; kk++) {
            unsigned a[4], b[8][2];
            ldm_x4(a[0], a[1], a[2], a[3],
                   &Ps[(w * 16 + a_row) * PH + kk * 16 + a_ko]);
            #pragma unroll
            for (int nj = 0; nj < 4; nj++)
                ldm_x4(b[2*nj][0], b[2*nj][1], b[2*nj+1][0], b[2*nj+1][1],
                       &Vt[(nj * 16 + b_nr) * PH + kk * 16 + b_ko]);
            #pragma unroll
            for (int ni = 0; ni < 8; ni++)
                mma_f16(o[ni], a, b[ni]);
        }
        __syncthreads();   // trailing barrier kept (R13 lesson)
    }

    // normalize + write ctx [B, S, H*DK] as half
    const int b_idx = bh / NH, h = bh % NH;
    const float inv0 = 1.0f / l0, inv1 = 1.0f / l1;
    const int r1 = w * 16 + lq, r2 = r1 + 8;
    __half* c1 = g_Ch + (size_t)(b_idx * SEQ + qt * 128 + r1) * DMODEL + h * DK;
    __half* c2 = g_Ch + (size_t)(b_idx * SEQ + qt * 128 + r2) * DMODEL + h * DK;
    #pragma unroll
    for (int ni = 0; ni < 8; ni++) {
        int c = ni * 8 + 2 * lr;
        *(__half2*)(c1 + c) = __floats2half2_rn(o[ni][0] * inv0, o[ni][1] * inv0);
        *(__half2*)(c2 + c) = __floats2half2_rn(o[ni][2] * inv1, o[ni][3] * inv1);
    }
}

// ---------------------------------------------------------------------------
// Output projection: tile 128x128, 3-slot depth-2 ring, both barriers.
// grid (64, 8), block 256. dyn smem 61440 B.
// ---------------------------------------------------------------------------
__global__ void __launch_bounds__(256, 2) out_proj(
    const float* __restrict__ bo, float* __restrict__ out)
{
    extern __shared__ __align__(16) __half smh[];

    const int row0 = blockIdx.x * 128, n0 = blockIdx.y * 128;
    const int tid = threadIdx.x;
    const int w  = tid >> 5;
    const int l  = tid & 31;
    const int lr = l & 3;
    const int wm = w >> 1, wn = w & 1;

    const int a_row = l & 15;
    const int a_ko  = (l >> 4) << 3;
    const int b_nr  = (l & 7) + ((l >> 4) << 3);
    const int b_ko  = ((l >> 3) & 1) << 3;

    float acc[2][8][4] = {};

    auto stage = [&](int c, int s) {
        __half* As = smh + s * STGH;
        __half* Bs = As + 128 * PW;
        int k0 = c * 32;
        #pragma unroll
        for (int i = 0; i < 2; i++) {
            int idx = tid + i * 256;
            int r = idx >> 2, j = idx & 3;
            cp16(&As[r * PW + j * 8], g_Ch + (size_t)(row0 + r) * DMODEL + k0 + j * 8);
        }
        #pragma unroll
        for (int i = 0; i < 2; i++) {
            int idx = tid + i * 256;
            int rn = idx >> 2, j = idx & 3;
            cp16(&Bs[rn * PW + j * 8], g_WoT + (size_t)(n0 + rn) * DMODEL + k0 + j * 8);
        }
        CP_COMMIT();
    };

    stage(0, 0);
    stage(1, 1);

    for (int c = 0; c < 32; c++) {
        if (c + 2 < 32)      { stage(c + 2, (c + 2) % 3); CP_WAIT2(); }
        else if (c + 1 < 32) { CP_WAIT1(); }
        else                 { CP_WAIT0(); }
        __syncthreads();

        const __half* As = smh + (c % 3) * STGH;
        const __half* Bs = As + 128 * PW;

        #pragma unroll
        for (int kk = 0; kk < 2; kk++) {
            unsigned a[2][4], b[8][2];
            #pragma unroll
            for (int mi = 0; mi < 2; mi++)
                ldm_x4(a[mi][0], a[mi][1], a[mi][2], a[mi][3],
                       &As[(wm * 32 + mi * 16 + a_row) * PW + kk * 16 + a_ko]);
            #pragma unroll
            for (int nj = 0; nj < 4; nj++)
                ldm_x4(b[2*nj][0], b[2*nj][1], b[2*nj+1][0], b[2*nj+1][1],
                       &Bs[(wn * 64 + nj * 16 + b_nr) * PW + kk * 16 + b_ko]);
            #pragma unroll
            for (int mi = 0; mi < 2; mi++)
                #pragma unroll
                for (int ni = 0; ni < 8; ni++)
                    mma_f16(acc[mi][ni], a[mi], b[ni]);
        }
        __syncthreads();
    }

    const int lq = l >> 2;
    #pragma unroll
    for (int mi = 0; mi < 2; mi++)
        #pragma unroll
        for (int rh = 0; rh < 2; rh++) {
            int m = row0 + wm * 32 + mi * 16 + lq + rh * 8;
            #pragma unroll
            for (int ni = 0; ni < 8; ni++) {
                int col = n0 + wn * 64 + ni * 8 + 2 * lr;
                float2 bv2 = *(const float2*)(bo + col);
                float2 v = make_float2(acc[mi][ni][rh * 2 + 0] + bv2.x,
                                       acc[mi][ni][rh * 2 + 1] + bv2.y);
                *(float2*)(out + (size_t)m * DMODEL + col) = v;
            }
        }
}

// ---------------------------------------------------------------------------
extern "C" void kernel_launch(void* const* d_in, const int* in_sizes, int n_in,
                              void* d_out, int out_size)
{
    const float* x  = (const float*)d_in[0];
    const float* Wq = (const float*)d_in[1];
    const float* bq = (const float*)d_in[2];
    const float* Wk = (const float*)d_in[3];
    const float* bk = (const float*)d_in[4];
    const float* Wv = (const float*)d_in[5];
    const float* bv = (const float*)d_in[6];
    const float* Wo = (const float*)d_in[7];
    const float* bo = (const float*)d_in[8];
    float* out = (float*)d_out;

    cudaFuncSetAttribute(qkv_proj,   cudaFuncAttributeMaxDynamicSharedMemorySize, GEMM_SMEM);
    cudaFuncSetAttribute(attn_flash, cudaFuncAttributeMaxDynamicSharedMemorySize, ATTN_SMEM);
    cudaFuncSetAttribute(out_proj,   cudaFuncAttributeMaxDynamicSharedMemorySize, GEMM_SMEM);

    __half* gx;
    cudaGetSymbolAddress((void**)&gx, g_Xh);

    const int NX4 = MROWS * DMODEL / 4;
    cvt_x_h<<<(NX4 + 255) / 256, 256>>>(x, gx, NX4);
    transpose_wqkv_t<<<dim3(32, 2, 48), dim3(32, 8)>>>(Wq, Wk, Wv);
    transpose_wo_t  <<<dim3(32, 32),    dim3(32, 8)>>>(Wo);

    qkv_proj<<<dim3(MROWS / 128, 24), 256, GEMM_SMEM>>>(bq, bk, bv);
    attn_flash<<<dim3(SEQ / 128, BATCH * NH), 256, ATTN_SMEM>>>();
    out_proj<<<dim3(MROWS / 128, 8), 256, GEMM_SMEM>>>(bo, out);
}